// round 12
// baseline (speedup 1.0000x reference)
#include <cuda_runtime.h>
#include <cuda_bf16.h>
#include <stdint.h>

#define C_DIM   1280
#define N_DIM   2560             // 2 conv planes * C, plane-major rows
#define B_PAT   2048
#define P_TOT   12288            // B_PAT * 6 pairs
#define M_ROWS  8192             // B_PAT * 4 images
#define PC_STRIDE 15728640u      // P_TOT * C_DIM
#define NCNT    15728640
#define NTHREADS_TF 163840u      // 1280 CTAs * 128 threefry threads

// ---------------- scratch (no cudaMalloc allowed) ----------------
__device__ __nv_bfloat16 g_Ahi[M_ROWS * C_DIM];
__device__ __nv_bfloat16 g_Alo[M_ROWS * C_DIM];
__device__ __nv_bfloat16 g_Bhi[N_DIM * C_DIM];
__device__ __nv_bfloat16 g_Blo[N_DIM * C_DIM];
__device__ float         g_Y[M_ROWS * N_DIM];
__device__ uint8_t       g_cnt[NCNT];            // dropout popcounts, 0..5
__device__ float         g_dots[P_TOT * 3];

__device__ __forceinline__ uint32_t smem_u32(const void* p) {
    uint32_t a;
    asm("{ .reg .u64 t; cvta.to.shared.u64 t, %1; cvt.u32.u64 %0, t; }" : "=r"(a) : "l"(p));
    return a;
}
#define SW128(o)   ((o) ^ (((o) >> 3) & 0x70))
#define GBAR()     asm volatile("bar.sync 1, 256;" ::: "memory")   // gemm warps only

__device__ __forceinline__ void cp_async16(uint32_t dst, const void* src) {
    asm volatile("cp.async.cg.shared.global [%0], [%1], 16;" :: "r"(dst), "l"(src));
}
__device__ __forceinline__ void ldsm4(uint32_t* r, uint32_t addr) {
    asm volatile("ldmatrix.sync.aligned.m8n8.x4.shared.b16 {%0,%1,%2,%3}, [%4];"
                 : "=r"(r[0]), "=r"(r[1]), "=r"(r[2]), "=r"(r[3]) : "r"(addr));
}
__device__ __forceinline__ void mma_bf16(float* c, const uint32_t* a, uint32_t b0, uint32_t b1) {
    asm volatile(
        "mma.sync.aligned.m16n8k16.row.col.f32.bf16.bf16.f32 "
        "{%0,%1,%2,%3}, {%4,%5,%6,%7}, {%8,%9}, {%0,%1,%2,%3};"
        : "+f"(c[0]), "+f"(c[1]), "+f"(c[2]), "+f"(c[3])
        : "r"(a[0]), "r"(a[1]), "r"(a[2]), "r"(a[3]), "r"(b0), "r"(b1));
}

// ---------------- Threefry-2x32 (key = (0,42)) ----------------
__device__ __forceinline__ uint32_t rotl32(uint32_t x, int r) { return __funnelshift_l(x, x, r); }
__device__ __forceinline__ uint2 tf2x32(uint32_t v0, uint32_t v1) {
    const uint32_t ks0 = 0u, ks1 = 42u, ks2 = 0x1BD11BDAu ^ 42u;
    uint32_t x0 = v0 + ks0, x1 = v1 + ks1;
#define TFR(r) { x0 += x1; x1 = rotl32(x1, r); x1 ^= x0; }
    TFR(13) TFR(15) TFR(26) TFR(6)  x0 += ks1; x1 += ks2 + 1u;
    TFR(17) TFR(29) TFR(16) TFR(24) x0 += ks2; x1 += ks0 + 2u;
    TFR(13) TFR(15) TFR(26) TFR(6)  x0 += ks0; x1 += ks1 + 3u;
    TFR(17) TFR(29) TFR(16) TFR(24) x0 += ks1; x1 += ks2 + 4u;
    TFR(13) TFR(15) TFR(26) TFR(6)  x0 += ks2; x1 += ks0 + 5u;
#undef TFR
    return make_uint2(x0, x1);
}
__device__ __forceinline__ uint32_t cnt5(uint32_t e) {
    uint32_t cnt = 0;
#pragma unroll
    for (int d = 0; d < 5; d++) {
        uint2 r = tf2x32(0u, e + (uint32_t)d * PC_STRIDE);
        cnt += (~(r.x ^ r.y)) >> 31;
    }
    return cnt;
}

// ---------------- pre-convert: fp32 -> bf16 hi/lo splits ----------------
__global__ __launch_bounds__(256) void convert_x(const float* __restrict__ x) {
    int i = blockIdx.x * 256 + threadIdx.x;          // over M_ROWS*C_DIM/4
    float4 v = ((const float4*)x)[i];
    float f[4] = {v.x, v.y, v.z, v.w};
    __nv_bfloat16 h[4], l[4];
#pragma unroll
    for (int j = 0; j < 4; j++) {
        h[j] = __float2bfloat16(f[j]);
        l[j] = __float2bfloat16(f[j] - __bfloat162float(h[j]));
    }
    ((__nv_bfloat162*)g_Ahi)[2 * i + 0] = __nv_bfloat162(h[0], h[1]);
    ((__nv_bfloat162*)g_Ahi)[2 * i + 1] = __nv_bfloat162(h[2], h[3]);
    ((__nv_bfloat162*)g_Alo)[2 * i + 0] = __nv_bfloat162(l[0], l[1]);
    ((__nv_bfloat162*)g_Alo)[2 * i + 1] = __nv_bfloat162(l[2], l[3]);
}

// B row n: n<1280 -> Wc[n][i][0]; n>=1280 -> Wc[n-1280][i][1]
__global__ __launch_bounds__(256) void convert_w(const float* __restrict__ Wc) {
    int idx = blockIdx.x * 256 + threadIdx.x;        // over C_DIM*C_DIM
    int o = idx / C_DIM, i = idx - o * C_DIM;
    float2 v = ((const float2*)Wc)[o * C_DIM + i];   // (plane0, plane1)
    __nv_bfloat16 h0 = __float2bfloat16(v.x);
    __nv_bfloat16 h1 = __float2bfloat16(v.y);
    g_Bhi[(size_t)o * C_DIM + i]          = h0;
    g_Bhi[(size_t)(1280 + o) * C_DIM + i] = h1;
    g_Blo[(size_t)o * C_DIM + i]          = __float2bfloat16(v.x - __bfloat162float(h0));
    g_Blo[(size_t)(1280 + o) * C_DIM + i] = __float2bfloat16(v.y - __bfloat162float(h1));
}

// ---------------- fused GEMM + threefry (warp-specialized) ----------------
// Warps 0-3  (LOWEST wid -> lowest arbiter priority): threefry cnt production.
//             One warp per SMSP; backfills the gemm warps' idle issue slots.
// Warps 4-11 (higher wid -> arbiter priority): mma.sync split-bf16 GEMM,
//             CTA tile 128x128, BK=64, double-buffered cp.async,
//             named barrier (bar.sync 1, 256).
#define AHI_OFF 0
#define ALO_OFF 16384
#define BHI_OFF 32768
#define BLO_OFF 49152
#define BUF_SZ  65536
#define GSMEM   131072

__global__ __launch_bounds__(384) void gemm_mma_kernel() {
    extern __shared__ __align__(1024) char smem[];
    const int tid = threadIdx.x;

    // ---- threefry warps (0..3): lowest priority, pure backfill ----
    if (tid < 128) {
        const uint32_t t4 = (uint32_t)(blockIdx.y * gridDim.x + blockIdx.x) * 128u
                          + (uint32_t)tid;
#pragma unroll 4
        for (int s = 0; s < 24; s++) {
            const uint32_t e4 = t4 + (uint32_t)s * NTHREADS_TF;
            const uint32_t f  = e4 * 4u;
            uchar4 pk;
            pk.x = (uint8_t)cnt5(f + 0u);
            pk.y = (uint8_t)cnt5(f + 1u);
            pk.z = (uint8_t)cnt5(f + 2u);
            pk.w = (uint8_t)cnt5(f + 3u);
            ((uchar4*)g_cnt)[e4] = pk;
        }
        return;
    }

    // ---- gemm warps (4..11) ----
    const int gtid = tid - 128;                       // 0..255
    const uint32_t sb = smem_u32(smem);
    const int gwid = gtid >> 5, lane = gtid & 31;
    const int m0 = blockIdx.y * 128, n0 = blockIdx.x * 128;
    const int wm = (gwid >> 1) * 32, wn = (gwid & 1) * 64;

    float acc[2][8][4];
#pragma unroll
    for (int t = 0; t < 2; t++)
#pragma unroll
        for (int j = 0; j < 8; j++)
#pragma unroll
            for (int q = 0; q < 4; q++) acc[t][j][q] = 0.f;

    const int lrow_base = gtid >> 3;
    const int lcol = (gtid & 7) * 8;

    auto load_chunk = [&](int kc, int buf) {
        const uint32_t sbase = sb + buf * BUF_SZ;
        const int k0 = kc * 64;
#pragma unroll
        for (int it = 0; it < 4; it++) {
            const int row = lrow_base + it * 32;
            const uint32_t so = SW128((uint32_t)(row * 128 + lcol * 2));
            const size_t goA = (size_t)(m0 + row) * C_DIM + k0 + lcol;
            const size_t goB = (size_t)(n0 + row) * C_DIM + k0 + lcol;
            cp_async16(sbase + AHI_OFF + so, g_Ahi + goA);
            cp_async16(sbase + ALO_OFF + so, g_Alo + goA);
            cp_async16(sbase + BHI_OFF + so, g_Bhi + goB);
            cp_async16(sbase + BLO_OFF + so, g_Blo + goB);
        }
    };

    const uint32_t a_row = wm + (lane & 15);
    const uint32_t a_k8  = (lane >> 4) * 8;
    const uint32_t b_row = wn + ((lane >> 4) << 3) + (lane & 7);
    const uint32_t b_k8  = (lane & 8);

    load_chunk(0, 0);
    asm volatile("cp.async.commit_group;" ::: "memory");

    for (int kc = 0; kc < 20; kc++) {
        const int buf = kc & 1;
        if (kc < 19) {
            load_chunk(kc + 1, buf ^ 1);
            asm volatile("cp.async.commit_group;" ::: "memory");
            asm volatile("cp.async.wait_group 1;" ::: "memory");
        } else {
            asm volatile("cp.async.wait_group 0;" ::: "memory");
        }
        GBAR();

        const uint32_t sbase = sb + buf * BUF_SZ;
#pragma unroll
        for (int ks = 0; ks < 4; ks++) {
            uint32_t ahi[2][4], alo[2][4], bhi[4][4], blo[4][4];
#pragma unroll
            for (int t = 0; t < 2; t++) {
                uint32_t off = SW128(((a_row + t * 16) << 7) + ((ks * 16 + a_k8) << 1));
                ldsm4(ahi[t], sbase + AHI_OFF + off);
                ldsm4(alo[t], sbase + ALO_OFF + off);
            }
#pragma unroll
            for (int g = 0; g < 4; g++) {
                uint32_t off = SW128(((b_row + g * 16) << 7) + ((ks * 16 + b_k8) << 1));
                ldsm4(bhi[g], sbase + BHI_OFF + off);
                ldsm4(blo[g], sbase + BLO_OFF + off);
            }
#pragma unroll
            for (int t = 0; t < 2; t++)
#pragma unroll
                for (int j = 0; j < 8; j++) {
                    const uint32_t* bh = &bhi[j >> 1][(j & 1) * 2];
                    const uint32_t* bl = &blo[j >> 1][(j & 1) * 2];
                    mma_bf16(acc[t][j], ahi[t], bh[0], bh[1]);
                    mma_bf16(acc[t][j], ahi[t], bl[0], bl[1]);
                    mma_bf16(acc[t][j], alo[t], bh[0], bh[1]);
                }
        }
        GBAR();
    }

    // epilogue: acc -> g_Y
    const int mrow = m0 + wm + lane / 4;
    const int ncol = n0 + wn + (lane & 3) * 2;
#pragma unroll
    for (int t = 0; t < 2; t++)
#pragma unroll
        for (int j = 0; j < 8; j++) {
            float* y0 = g_Y + (size_t)(mrow + t * 16) * N_DIM + ncol + j * 8;
            *(float2*)y0                       = make_float2(acc[t][j][0], acc[t][j][1]);
            *(float2*)(y0 + 8 * (size_t)N_DIM) = make_float2(acc[t][j][2], acc[t][j][3]);
        }
}

// ---------------- lean head-dot pass (cnt precomputed) ----------------
__global__ __launch_bounds__(256) void mask_dot_kernel(const float* __restrict__ bc,
                                                       const float* __restrict__ w0,
                                                       const float* __restrict__ w1,
                                                       const float* __restrict__ w2) {
    const int gw   = (blockIdx.x * 256 + threadIdx.x) >> 5;
    const int lane = threadIdx.x & 31;
    if (gw >= P_TOT) return;
    const int p = gw, g = p / 6, q = p - g * 6;
    const int ii_t[6] = {0, 0, 0, 1, 1, 2};
    const int jj_t[6] = {1, 2, 3, 2, 3, 3};
    const float* ya = g_Y + (size_t)(g * 4 + ii_t[q]) * N_DIM;          // plane 0
    const float* yb = g_Y + (size_t)(g * 4 + jj_t[q]) * N_DIM + 1280;   // plane 1
    const uint8_t* cp = g_cnt + (size_t)p * C_DIM;

    float a0 = 0.f, a1 = 0.f, a2 = 0.f;
#pragma unroll
    for (int it = 0; it < 10; it++) {
        const int c = it * 128 + lane * 4;
        float4 va = *(const float4*)(ya + c);
        float4 vb = *(const float4*)(yb + c);
        float4 fb = *(const float4*)(bc + c);
        float4 v0 = *(const float4*)(w0 + c);
        float4 v1 = *(const float4*)(w1 + c);
        float4 v2 = *(const float4*)(w2 + c);
        uchar4 cv = *(const uchar4*)(cp + c);
        float xf[4] = {va.x + vb.x + fb.x, va.y + vb.y + fb.y,
                       va.z + vb.z + fb.z, va.w + vb.w + fb.w};
        float cf[4] = {(float)cv.x, (float)cv.y, (float)cv.z, (float)cv.w};
        float w0a[4] = {v0.x, v0.y, v0.z, v0.w};
        float w1a[4] = {v1.x, v1.y, v1.z, v1.w};
        float w2a[4] = {v2.x, v2.y, v2.z, v2.w};
#pragma unroll
        for (int j = 0; j < 4; j++) {
            float t = fmaxf(xf[j], 0.f) * cf[j];
            a0 = fmaf(t, w0a[j], a0);
            a1 = fmaf(t, w1a[j], a1);
            a2 = fmaf(t, w2a[j], a2);
        }
    }
#pragma unroll
    for (int off = 16; off > 0; off >>= 1) {
        a0 += __shfl_down_sync(0xffffffffu, a0, off);
        a1 += __shfl_down_sync(0xffffffffu, a1, off);
        a2 += __shfl_down_sync(0xffffffffu, a2, off);
    }
    if (lane == 0) {
        g_dots[p * 3 + 0] = a0;
        g_dots[p * 3 + 1] = a1;
        g_dots[p * 3 + 2] = a2;
    }
}

__global__ void finalize_kernel(const float* __restrict__ b0, const float* __restrict__ b1,
                                const float* __restrict__ b2, float* __restrict__ out) {
    int idx = blockIdx.x * blockDim.x + threadIdx.x;
    if (idx >= B_PAT * 3) return;
    int b = idx / 3, h = idx - b * 3;
    float s = 0.f;
#pragma unroll
    for (int qq = 0; qq < 6; qq++) s += g_dots[(b * 6 + qq) * 3 + h];
    float bias = (h == 0) ? b0[0] : (h == 1 ? b1[0] : b2[0]);
    out[idx] = bias + s * (1.0f / 15.0f);
}

extern "C" void kernel_launch(void* const* d_in, const int* in_sizes, int n_in,
                              void* d_out, int out_size) {
    const float* x  = (const float*)d_in[0];
    const float* Wc = (const float*)d_in[2];
    const float* bc = (const float*)d_in[3];
    const float* W0 = (const float*)d_in[4];
    const float* b0 = (const float*)d_in[5];
    const float* W1 = (const float*)d_in[6];
    const float* b1 = (const float*)d_in[7];
    const float* W2 = (const float*)d_in[8];
    const float* b2 = (const float*)d_in[9];
    float* out = (float*)d_out;

    static bool init = false;
    if (!init) {
        cudaFuncSetAttribute(gemm_mma_kernel, cudaFuncAttributeMaxDynamicSharedMemorySize, GSMEM);
        init = true;
    }

    convert_x<<<(M_ROWS * C_DIM / 4) / 256, 256>>>(x);
    convert_w<<<(C_DIM * C_DIM) / 256, 256>>>(Wc);
    gemm_mma_kernel<<<dim3(N_DIM / 128, M_ROWS / 128), 384, GSMEM>>>();
    mask_dot_kernel<<<(P_TOT * 32) / 256, 256>>>(bc, W0, W1, W2);
    finalize_kernel<<<(B_PAT * 3 + 255) / 256, 256>>>(b0, b1, b2, out);
}

// round 14
// speedup vs baseline: 1.2603x; 1.2603x over previous
#include <cuda_runtime.h>
#include <cuda_fp16.h>
#include <stdint.h>

#define C_DIM   1280
#define N_DIM   2560             // 2 conv planes * C, plane-major rows
#define B_PAT   2048
#define P_TOT   12288            // B_PAT * 6 pairs
#define M_ROWS  8192             // B_PAT * 4 images
#define PC_STRIDE 15728640u      // P_TOT * C_DIM
#define NCNT    15728640
#define NTHREADS_TF 163840u      // 1280 CTAs * 128 threefry threads

// ---------------- scratch (no cudaMalloc allowed) ----------------
__device__ __half  g_A[M_ROWS * C_DIM];          // x in fp16
__device__ __half  g_B[N_DIM * C_DIM];           // Wc planes in fp16
__device__ float   g_Y[M_ROWS * N_DIM];
__device__ uint8_t g_cnt[NCNT];                  // dropout popcounts, 0..5
__device__ float   g_dots[P_TOT * 3];

__device__ __forceinline__ uint32_t smem_u32(const void* p) {
    uint32_t a;
    asm("{ .reg .u64 t; cvta.to.shared.u64 t, %1; cvt.u32.u64 %0, t; }" : "=r"(a) : "l"(p));
    return a;
}
#define SW128(o)   ((o) ^ (((o) >> 3) & 0x70))
#define GBAR()     asm volatile("bar.sync 1, 256;" ::: "memory")   // gemm warps only

__device__ __forceinline__ void cp_async16(uint32_t dst, const void* src) {
    asm volatile("cp.async.cg.shared.global [%0], [%1], 16;" :: "r"(dst), "l"(src));
}
__device__ __forceinline__ void ldsm4(uint32_t* r, uint32_t addr) {
    asm volatile("ldmatrix.sync.aligned.m8n8.x4.shared.b16 {%0,%1,%2,%3}, [%4];"
                 : "=r"(r[0]), "=r"(r[1]), "=r"(r[2]), "=r"(r[3]) : "r"(addr));
}
__device__ __forceinline__ void mma_f16(float* c, const uint32_t* a, uint32_t b0, uint32_t b1) {
    asm volatile(
        "mma.sync.aligned.m16n8k16.row.col.f32.f16.f16.f32 "
        "{%0,%1,%2,%3}, {%4,%5,%6,%7}, {%8,%9}, {%0,%1,%2,%3};"
        : "+f"(c[0]), "+f"(c[1]), "+f"(c[2]), "+f"(c[3])
        : "r"(a[0]), "r"(a[1]), "r"(a[2]), "r"(a[3]), "r"(b0), "r"(b1));
}

// ---------------- Threefry-2x32 (key = (0,42)) ----------------
__device__ __forceinline__ uint32_t rotl32(uint32_t x, int r) { return __funnelshift_l(x, x, r); }
__device__ __forceinline__ uint2 tf2x32(uint32_t v0, uint32_t v1) {
    const uint32_t ks0 = 0u, ks1 = 42u, ks2 = 0x1BD11BDAu ^ 42u;
    uint32_t x0 = v0 + ks0, x1 = v1 + ks1;
#define TFR(r) { x0 += x1; x1 = rotl32(x1, r); x1 ^= x0; }
    TFR(13) TFR(15) TFR(26) TFR(6)  x0 += ks1; x1 += ks2 + 1u;
    TFR(17) TFR(29) TFR(16) TFR(24) x0 += ks2; x1 += ks0 + 2u;
    TFR(13) TFR(15) TFR(26) TFR(6)  x0 += ks0; x1 += ks1 + 3u;
    TFR(17) TFR(29) TFR(16) TFR(24) x0 += ks1; x1 += ks2 + 4u;
    TFR(13) TFR(15) TFR(26) TFR(6)  x0 += ks2; x1 += ks0 + 5u;
#undef TFR
    return make_uint2(x0, x1);
}
__device__ __forceinline__ uint32_t cnt5(uint32_t e) {
    uint32_t cnt = 0;
#pragma unroll
    for (int d = 0; d < 5; d++) {
        uint2 r = tf2x32(0u, e + (uint32_t)d * PC_STRIDE);
        cnt += (~(r.x ^ r.y)) >> 31;
    }
    return cnt;
}

// ---------------- pre-convert: fp32 -> fp16 ----------------
__global__ __launch_bounds__(256) void convert_x(const float* __restrict__ x) {
    int i = blockIdx.x * 256 + threadIdx.x;          // over M_ROWS*C_DIM/4
    float4 v = ((const float4*)x)[i];
    ((__half2*)g_A)[2 * i + 0] = __floats2half2_rn(v.x, v.y);
    ((__half2*)g_A)[2 * i + 1] = __floats2half2_rn(v.z, v.w);
}

// B row n: n<1280 -> Wc[n][i][0]; n>=1280 -> Wc[n-1280][i][1]
__global__ __launch_bounds__(256) void convert_w(const float* __restrict__ Wc) {
    int idx = blockIdx.x * 256 + threadIdx.x;        // over C_DIM*C_DIM
    int o = idx / C_DIM, i = idx - o * C_DIM;
    float2 v = ((const float2*)Wc)[o * C_DIM + i];   // (plane0, plane1)
    g_B[(size_t)o * C_DIM + i]          = __float2half_rn(v.x);
    g_B[(size_t)(1280 + o) * C_DIM + i] = __float2half_rn(v.y);
}

// ---------------- fused GEMM + threefry (warp-specialized) ----------------
// Warps 0-3: threefry cnt production (the long pole; gemm hides under it).
// Warps 4-11: fp16 single-product mma.sync GEMM, CTA tile 128x128, BK=64,
//             3-stage cp.async pipeline, ONE named barrier per chunk.
#define A_OFF   0
#define B_OFF   16384
#define BUF_SZ  32768
#define GSMEM   98304

__global__ __launch_bounds__(384) void gemm_mma_kernel() {
    extern __shared__ __align__(1024) char smem[];
    const int tid = threadIdx.x;

    // ---- threefry warps (0..3) ----
    if (tid < 128) {
        const uint32_t t4 = (uint32_t)(blockIdx.y * gridDim.x + blockIdx.x) * 128u
                          + (uint32_t)tid;
#pragma unroll 4
        for (int s = 0; s < 24; s++) {
            const uint32_t e4 = t4 + (uint32_t)s * NTHREADS_TF;
            const uint32_t f  = e4 * 4u;
            uchar4 pk;
            pk.x = (uint8_t)cnt5(f + 0u);
            pk.y = (uint8_t)cnt5(f + 1u);
            pk.z = (uint8_t)cnt5(f + 2u);
            pk.w = (uint8_t)cnt5(f + 3u);
            ((uchar4*)g_cnt)[e4] = pk;
        }
        return;
    }

    // ---- gemm warps (4..11) ----
    const int gtid = tid - 128;                       // 0..255
    const uint32_t sb = smem_u32(smem);
    const int gwid = gtid >> 5, lane = gtid & 31;
    const int m0 = blockIdx.y * 128, n0 = blockIdx.x * 128;
    const int wm = (gwid >> 1) * 32, wn = (gwid & 1) * 64;

    float acc[2][8][4];
#pragma unroll
    for (int t = 0; t < 2; t++)
#pragma unroll
        for (int j = 0; j < 8; j++)
#pragma unroll
            for (int q = 0; q < 4; q++) acc[t][j][q] = 0.f;

    const int lrow_base = gtid >> 3;                  // 0..31
    const int lcol = (gtid & 7) * 8;                  // fp16 elems (16B granule)

    auto load_chunk = [&](int kc, int buf) {
        const uint32_t sbase = sb + buf * BUF_SZ;
        const int k0 = kc * 64;
#pragma unroll
        for (int it = 0; it < 4; it++) {
            const int row = lrow_base + it * 32;
            const uint32_t so = SW128((uint32_t)(row * 128 + lcol * 2));
            cp_async16(sbase + A_OFF + so, g_A + (size_t)(m0 + row) * C_DIM + k0 + lcol);
            cp_async16(sbase + B_OFF + so, g_B + (size_t)(n0 + row) * C_DIM + k0 + lcol);
        }
    };

    const uint32_t a_row = wm + (lane & 15);
    const uint32_t a_k8  = (lane >> 4) * 8;
    const uint32_t b_row = wn + ((lane >> 4) << 3) + (lane & 7);
    const uint32_t b_k8  = (lane & 8);

    load_chunk(0, 0);
    asm volatile("cp.async.commit_group;" ::: "memory");
    load_chunk(1, 1);
    asm volatile("cp.async.commit_group;" ::: "memory");

    for (int kc = 0; kc < 20; kc++) {
        asm volatile("cp.async.wait_group 1;" ::: "memory");  // chunk kc resident
        GBAR();                                               // data visible + prev compute done
        if (kc + 2 < 20) load_chunk(kc + 2, (kc + 2) % 3);    // overwrite of buf used in kc-1: safe post-GBAR
        asm volatile("cp.async.commit_group;" ::: "memory");  // unconditional (uniform group count)

        const uint32_t sbase = sb + (kc % 3) * BUF_SZ;
#pragma unroll
        for (int ks = 0; ks < 4; ks++) {
            uint32_t a[2][4], b[4][4];
#pragma unroll
            for (int t = 0; t < 2; t++) {
                uint32_t off = SW128(((a_row + t * 16) << 7) + ((ks * 16 + a_k8) << 1));
                ldsm4(a[t], sbase + A_OFF + off);
            }
#pragma unroll
            for (int g = 0; g < 4; g++) {
                uint32_t off = SW128(((b_row + g * 16) << 7) + ((ks * 16 + b_k8) << 1));
                ldsm4(b[g], sbase + B_OFF + off);
            }
#pragma unroll
            for (int t = 0; t < 2; t++)
#pragma unroll
                for (int j = 0; j < 8; j++)
                    mma_f16(acc[t][j], a[t], b[j >> 1][(j & 1) * 2], b[j >> 1][(j & 1) * 2 + 1]);
        }
    }

    // epilogue: acc -> g_Y
    const int mrow = m0 + wm + lane / 4;
    const int ncol = n0 + wn + (lane & 3) * 2;
#pragma unroll
    for (int t = 0; t < 2; t++)
#pragma unroll
        for (int j = 0; j < 8; j++) {
            float* y0 = g_Y + (size_t)(mrow + t * 16) * N_DIM + ncol + j * 8;
            *(float2*)y0                       = make_float2(acc[t][j][0], acc[t][j][1]);
            *(float2*)(y0 + 8 * (size_t)N_DIM) = make_float2(acc[t][j][2], acc[t][j][3]);
        }
}

// ---------------- lean head-dot pass (cnt precomputed) ----------------
__global__ __launch_bounds__(256) void mask_dot_kernel(const float* __restrict__ bc,
                                                       const float* __restrict__ w0,
                                                       const float* __restrict__ w1,
                                                       const float* __restrict__ w2) {
    const int gw   = (blockIdx.x * 256 + threadIdx.x) >> 5;
    const int lane = threadIdx.x & 31;
    if (gw >= P_TOT) return;
    const int p = gw, g = p / 6, q = p - g * 6;
    const int ii_t[6] = {0, 0, 0, 1, 1, 2};
    const int jj_t[6] = {1, 2, 3, 2, 3, 3};
    const float* ya = g_Y + (size_t)(g * 4 + ii_t[q]) * N_DIM;          // plane 0
    const float* yb = g_Y + (size_t)(g * 4 + jj_t[q]) * N_DIM + 1280;   // plane 1
    const uint8_t* cp = g_cnt + (size_t)p * C_DIM;

    float a0 = 0.f, a1 = 0.f, a2 = 0.f;
#pragma unroll
    for (int it = 0; it < 10; it++) {
        const int c = it * 128 + lane * 4;
        float4 va = *(const float4*)(ya + c);
        float4 vb = *(const float4*)(yb + c);
        float4 fb = *(const float4*)(bc + c);
        float4 v0 = *(const float4*)(w0 + c);
        float4 v1 = *(const float4*)(w1 + c);
        float4 v2 = *(const float4*)(w2 + c);
        uchar4 cv = *(const uchar4*)(cp + c);
        float xf[4] = {va.x + vb.x + fb.x, va.y + vb.y + fb.y,
                       va.z + vb.z + fb.z, va.w + vb.w + fb.w};
        float cf[4] = {(float)cv.x, (float)cv.y, (float)cv.z, (float)cv.w};
        float w0a[4] = {v0.x, v0.y, v0.z, v0.w};
        float w1a[4] = {v1.x, v1.y, v1.z, v1.w};
        float w2a[4] = {v2.x, v2.y, v2.z, v2.w};
#pragma unroll
        for (int j = 0; j < 4; j++) {
            float t = fmaxf(xf[j], 0.f) * cf[j];
            a0 = fmaf(t, w0a[j], a0);
            a1 = fmaf(t, w1a[j], a1);
            a2 = fmaf(t, w2a[j], a2);
        }
    }
#pragma unroll
    for (int off = 16; off > 0; off >>= 1) {
        a0 += __shfl_down_sync(0xffffffffu, a0, off);
        a1 += __shfl_down_sync(0xffffffffu, a1, off);
        a2 += __shfl_down_sync(0xffffffffu, a2, off);
    }
    if (lane == 0) {
        g_dots[p * 3 + 0] = a0;
        g_dots[p * 3 + 1] = a1;
        g_dots[p * 3 + 2] = a2;
    }
}

__global__ void finalize_kernel(const float* __restrict__ b0, const float* __restrict__ b1,
                                const float* __restrict__ b2, float* __restrict__ out) {
    int idx = blockIdx.x * blockDim.x + threadIdx.x;
    if (idx >= B_PAT * 3) return;
    int b = idx / 3, h = idx - b * 3;
    float s = 0.f;
#pragma unroll
    for (int qq = 0; qq < 6; qq++) s += g_dots[(b * 6 + qq) * 3 + h];
    float bias = (h == 0) ? b0[0] : (h == 1 ? b1[0] : b2[0]);
    out[idx] = bias + s * (1.0f / 15.0f);
}

extern "C" void kernel_launch(void* const* d_in, const int* in_sizes, int n_in,
                              void* d_out, int out_size) {
    const float* x  = (const float*)d_in[0];
    const float* Wc = (const float*)d_in[2];
    const float* bc = (const float*)d_in[3];
    const float* W0 = (const float*)d_in[4];
    const float* b0 = (const float*)d_in[5];
    const float* W1 = (const float*)d_in[6];
    const float* b1 = (const float*)d_in[7];
    const float* W2 = (const float*)d_in[8];
    const float* b2 = (const float*)d_in[9];
    float* out = (float*)d_out;

    static bool init = false;
    if (!init) {
        cudaFuncSetAttribute(gemm_mma_kernel, cudaFuncAttributeMaxDynamicSharedMemorySize, GSMEM);
        init = true;
    }

    convert_x<<<(M_ROWS * C_DIM / 4) / 256, 256>>>(x);
    convert_w<<<(C_DIM * C_DIM) / 256, 256>>>(Wc);
    gemm_mma_kernel<<<dim3(N_DIM / 128, M_ROWS / 128), 384, GSMEM>>>();
    mask_dot_kernel<<<(P_TOT * 32) / 256, 256>>>(bc, W0, W1, W2);
    finalize_kernel<<<(B_PAT * 3 + 255) / 256, 256>>>(b0, b1, b2, out);
}

// round 15
// speedup vs baseline: 1.6591x; 1.3164x over previous
#include <cuda_runtime.h>
#include <cuda_fp16.h>
#include <stdint.h>

#define C_DIM   1280
#define N_DIM   2560             // 2 conv planes * C, plane-major rows
#define B_PAT   2048
#define P_TOT   12288            // B_PAT * 6 pairs
#define M_ROWS  8192             // B_PAT * 4 images
#define PC_STRIDE 15728640u      // P_TOT * C_DIM
#define NCNT    15728640
#define NTHREADS_TF 327680u      // 1280 CTAs * 256 threefry threads

// ---------------- scratch (no cudaMalloc allowed) ----------------
__device__ __half  g_A[M_ROWS * C_DIM];          // x in fp16
__device__ __half  g_B[N_DIM * C_DIM];           // Wc planes in fp16
__device__ float   g_Y[M_ROWS * N_DIM];
__device__ uint8_t g_cnt[NCNT];                  // dropout popcounts, 0..5
__device__ float   g_dots[P_TOT * 3];

__device__ __forceinline__ uint32_t smem_u32(const void* p) {
    uint32_t a;
    asm("{ .reg .u64 t; cvta.to.shared.u64 t, %1; cvt.u32.u64 %0, t; }" : "=r"(a) : "l"(p));
    return a;
}
#define SW128(o)   ((o) ^ (((o) >> 3) & 0x70))
#define GBAR()     asm volatile("bar.sync 1, 256;" ::: "memory")   // gemm warps only

__device__ __forceinline__ void cp_async16(uint32_t dst, const void* src) {
    asm volatile("cp.async.cg.shared.global [%0], [%1], 16;" :: "r"(dst), "l"(src));
}
__device__ __forceinline__ void ldsm4(uint32_t* r, uint32_t addr) {
    asm volatile("ldmatrix.sync.aligned.m8n8.x4.shared.b16 {%0,%1,%2,%3}, [%4];"
                 : "=r"(r[0]), "=r"(r[1]), "=r"(r[2]), "=r"(r[3]) : "r"(addr));
}
__device__ __forceinline__ void mma_f16(float* c, const uint32_t* a, uint32_t b0, uint32_t b1) {
    asm volatile(
        "mma.sync.aligned.m16n8k16.row.col.f32.f16.f16.f32 "
        "{%0,%1,%2,%3}, {%4,%5,%6,%7}, {%8,%9}, {%0,%1,%2,%3};"
        : "+f"(c[0]), "+f"(c[1]), "+f"(c[2]), "+f"(c[3])
        : "r"(a[0]), "r"(a[1]), "r"(a[2]), "r"(a[3]), "r"(b0), "r"(b1));
}

// ---------------- Threefry-2x32 (key = (0,42)) ----------------
__device__ __forceinline__ uint32_t rotl32(uint32_t x, int r) { return __funnelshift_l(x, x, r); }
__device__ __forceinline__ uint2 tf2x32(uint32_t v0, uint32_t v1) {
    const uint32_t ks0 = 0u, ks1 = 42u, ks2 = 0x1BD11BDAu ^ 42u;
    uint32_t x0 = v0 + ks0, x1 = v1 + ks1;
#define TFR(r) { x0 += x1; x1 = rotl32(x1, r); x1 ^= x0; }
    TFR(13) TFR(15) TFR(26) TFR(6)  x0 += ks1; x1 += ks2 + 1u;
    TFR(17) TFR(29) TFR(16) TFR(24) x0 += ks2; x1 += ks0 + 2u;
    TFR(13) TFR(15) TFR(26) TFR(6)  x0 += ks0; x1 += ks1 + 3u;
    TFR(17) TFR(29) TFR(16) TFR(24) x0 += ks1; x1 += ks2 + 4u;
    TFR(13) TFR(15) TFR(26) TFR(6)  x0 += ks2; x1 += ks0 + 5u;
#undef TFR
    return make_uint2(x0, x1);
}
__device__ __forceinline__ uint32_t cnt5(uint32_t e) {
    uint32_t cnt = 0;
#pragma unroll
    for (int d = 0; d < 5; d++) {
        uint2 r = tf2x32(0u, e + (uint32_t)d * PC_STRIDE);
        cnt += (~(r.x ^ r.y)) >> 31;
    }
    return cnt;
}

// ---------------- pre-convert: fp32 -> fp16 ----------------
__global__ __launch_bounds__(256) void convert_x(const float* __restrict__ x) {
    int i = blockIdx.x * 256 + threadIdx.x;          // over M_ROWS*C_DIM/4
    float4 v = ((const float4*)x)[i];
    ((__half2*)g_A)[2 * i + 0] = __floats2half2_rn(v.x, v.y);
    ((__half2*)g_A)[2 * i + 1] = __floats2half2_rn(v.z, v.w);
}

// B row n: n<1280 -> Wc[n][i][0]; n>=1280 -> Wc[n-1280][i][1]
__global__ __launch_bounds__(256) void convert_w(const float* __restrict__ Wc) {
    int idx = blockIdx.x * 256 + threadIdx.x;        // over C_DIM*C_DIM
    int o = idx / C_DIM, i = idx - o * C_DIM;
    float2 v = ((const float2*)Wc)[o * C_DIM + i];   // (plane0, plane1)
    g_B[(size_t)o * C_DIM + i]          = __float2half_rn(v.x);
    g_B[(size_t)(1280 + o) * C_DIM + i] = __float2half_rn(v.y);
}

// ---------------- fused GEMM + threefry (warp-specialized, 512 thr) --------
// Warps 0-7  (2 per SMSP): threefry cnt production — two warps interleave to
//            keep the alu pipe at its 1-op/2-cyc rate despite dep-chain stalls.
// Warps 8-15 (2 per SMSP): fp16 mma.sync GEMM, CTA tile 128x128, BK=64,
//            3-stage cp.async pipeline, one named barrier per chunk.
#define A_OFF   0
#define B_OFF   16384
#define BUF_SZ  32768
#define GSMEM   98304

__global__ __launch_bounds__(512) void gemm_mma_kernel() {
    extern __shared__ __align__(1024) char smem[];
    const int tid = threadIdx.x;

    // ---- threefry warps (0..7) ----
    if (tid < 256) {
        const uint32_t t4 = (uint32_t)(blockIdx.y * gridDim.x + blockIdx.x) * 256u
                          + (uint32_t)tid;
#pragma unroll 4
        for (int s = 0; s < 12; s++) {
            const uint32_t e4 = t4 + (uint32_t)s * NTHREADS_TF;
            const uint32_t f  = e4 * 4u;
            uchar4 pk;
            pk.x = (uint8_t)cnt5(f + 0u);
            pk.y = (uint8_t)cnt5(f + 1u);
            pk.z = (uint8_t)cnt5(f + 2u);
            pk.w = (uint8_t)cnt5(f + 3u);
            ((uchar4*)g_cnt)[e4] = pk;
        }
        return;
    }

    // ---- gemm warps (8..15) ----
    const int gtid = tid - 256;                       // 0..255
    const uint32_t sb = smem_u32(smem);
    const int gwid = gtid >> 5, lane = gtid & 31;
    const int m0 = blockIdx.y * 128, n0 = blockIdx.x * 128;
    const int wm = (gwid >> 1) * 32, wn = (gwid & 1) * 64;

    float acc[2][8][4];
#pragma unroll
    for (int t = 0; t < 2; t++)
#pragma unroll
        for (int j = 0; j < 8; j++)
#pragma unroll
            for (int q = 0; q < 4; q++) acc[t][j][q] = 0.f;

    const int lrow_base = gtid >> 3;                  // 0..31
    const int lcol = (gtid & 7) * 8;                  // fp16 elems (16B granule)

    auto load_chunk = [&](int kc, int buf) {
        const uint32_t sbase = sb + buf * BUF_SZ;
        const int k0 = kc * 64;
#pragma unroll
        for (int it = 0; it < 4; it++) {
            const int row = lrow_base + it * 32;
            const uint32_t so = SW128((uint32_t)(row * 128 + lcol * 2));
            cp_async16(sbase + A_OFF + so, g_A + (size_t)(m0 + row) * C_DIM + k0 + lcol);
            cp_async16(sbase + B_OFF + so, g_B + (size_t)(n0 + row) * C_DIM + k0 + lcol);
        }
    };

    const uint32_t a_row = wm + (lane & 15);
    const uint32_t a_k8  = (lane >> 4) * 8;
    const uint32_t b_row = wn + ((lane >> 4) << 3) + (lane & 7);
    const uint32_t b_k8  = (lane & 8);

    load_chunk(0, 0);
    asm volatile("cp.async.commit_group;" ::: "memory");
    load_chunk(1, 1);
    asm volatile("cp.async.commit_group;" ::: "memory");

    for (int kc = 0; kc < 20; kc++) {
        asm volatile("cp.async.wait_group 1;" ::: "memory");  // chunk kc resident
        GBAR();                                               // data visible + prev compute done
        if (kc + 2 < 20) load_chunk(kc + 2, (kc + 2) % 3);
        asm volatile("cp.async.commit_group;" ::: "memory");  // unconditional (uniform group count)

        const uint32_t sbase = sb + (kc % 3) * BUF_SZ;
#pragma unroll
        for (int ks = 0; ks < 4; ks++) {
            uint32_t a[2][4], b[4][4];
#pragma unroll
            for (int t = 0; t < 2; t++) {
                uint32_t off = SW128(((a_row + t * 16) << 7) + ((ks * 16 + a_k8) << 1));
                ldsm4(a[t], sbase + A_OFF + off);
            }
#pragma unroll
            for (int g = 0; g < 4; g++) {
                uint32_t off = SW128(((b_row + g * 16) << 7) + ((ks * 16 + b_k8) << 1));
                ldsm4(b[g], sbase + B_OFF + off);
            }
#pragma unroll
            for (int t = 0; t < 2; t++)
#pragma unroll
                for (int j = 0; j < 8; j++)
                    mma_f16(acc[t][j], a[t], b[j >> 1][(j & 1) * 2], b[j >> 1][(j & 1) * 2 + 1]);
        }
    }

    // epilogue: acc -> g_Y
    const int mrow = m0 + wm + lane / 4;
    const int ncol = n0 + wn + (lane & 3) * 2;
#pragma unroll
    for (int t = 0; t < 2; t++)
#pragma unroll
        for (int j = 0; j < 8; j++) {
            float* y0 = g_Y + (size_t)(mrow + t * 16) * N_DIM + ncol + j * 8;
            *(float2*)y0                       = make_float2(acc[t][j][0], acc[t][j][1]);
            *(float2*)(y0 + 8 * (size_t)N_DIM) = make_float2(acc[t][j][2], acc[t][j][3]);
        }
}

// ---------------- lean head-dot pass (cnt precomputed) ----------------
__global__ __launch_bounds__(256) void mask_dot_kernel(const float* __restrict__ bc,
                                                       const float* __restrict__ w0,
                                                       const float* __restrict__ w1,
                                                       const float* __restrict__ w2) {
    const int gw   = (blockIdx.x * 256 + threadIdx.x) >> 5;
    const int lane = threadIdx.x & 31;
    if (gw >= P_TOT) return;
    const int p = gw, g = p / 6, q = p - g * 6;
    const int ii_t[6] = {0, 0, 0, 1, 1, 2};
    const int jj_t[6] = {1, 2, 3, 2, 3, 3};
    const float* ya = g_Y + (size_t)(g * 4 + ii_t[q]) * N_DIM;          // plane 0
    const float* yb = g_Y + (size_t)(g * 4 + jj_t[q]) * N_DIM + 1280;   // plane 1
    const uint8_t* cp = g_cnt + (size_t)p * C_DIM;

    float a0 = 0.f, a1 = 0.f, a2 = 0.f;
#pragma unroll
    for (int it = 0; it < 10; it++) {
        const int c = it * 128 + lane * 4;
        float4 va = *(const float4*)(ya + c);
        float4 vb = *(const float4*)(yb + c);
        float4 fb = *(const float4*)(bc + c);
        float4 v0 = *(const float4*)(w0 + c);
        float4 v1 = *(const float4*)(w1 + c);
        float4 v2 = *(const float4*)(w2 + c);
        uchar4 cv = *(const uchar4*)(cp + c);
        float xf[4] = {va.x + vb.x + fb.x, va.y + vb.y + fb.y,
                       va.z + vb.z + fb.z, va.w + vb.w + fb.w};
        float cf[4] = {(float)cv.x, (float)cv.y, (float)cv.z, (float)cv.w};
        float w0a[4] = {v0.x, v0.y, v0.z, v0.w};
        float w1a[4] = {v1.x, v1.y, v1.z, v1.w};
        float w2a[4] = {v2.x, v2.y, v2.z, v2.w};
#pragma unroll
        for (int j = 0; j < 4; j++) {
            float t = fmaxf(xf[j], 0.f) * cf[j];
            a0 = fmaf(t, w0a[j], a0);
            a1 = fmaf(t, w1a[j], a1);
            a2 = fmaf(t, w2a[j], a2);
        }
    }
#pragma unroll
    for (int off = 16; off > 0; off >>= 1) {
        a0 += __shfl_down_sync(0xffffffffu, a0, off);
        a1 += __shfl_down_sync(0xffffffffu, a1, off);
        a2 += __shfl_down_sync(0xffffffffu, a2, off);
    }
    if (lane == 0) {
        g_dots[p * 3 + 0] = a0;
        g_dots[p * 3 + 1] = a1;
        g_dots[p * 3 + 2] = a2;
    }
}

__global__ void finalize_kernel(const float* __restrict__ b0, const float* __restrict__ b1,
                                const float* __restrict__ b2, float* __restrict__ out) {
    int idx = blockIdx.x * blockDim.x + threadIdx.x;
    if (idx >= B_PAT * 3) return;
    int b = idx / 3, h = idx - b * 3;
    float s = 0.f;
#pragma unroll
    for (int qq = 0; qq < 6; qq++) s += g_dots[(b * 6 + qq) * 3 + h];
    float bias = (h == 0) ? b0[0] : (h == 1 ? b1[0] : b2[0]);
    out[idx] = bias + s * (1.0f / 15.0f);
}

extern "C" void kernel_launch(void* const* d_in, const int* in_sizes, int n_in,
                              void* d_out, int out_size) {
    const float* x  = (const float*)d_in[0];
    const float* Wc = (const float*)d_in[2];
    const float* bc = (const float*)d_in[3];
    const float* W0 = (const float*)d_in[4];
    const float* b0 = (const float*)d_in[5];
    const float* W1 = (const float*)d_in[6];
    const float* b1 = (const float*)d_in[7];
    const float* W2 = (const float*)d_in[8];
    const float* b2 = (const float*)d_in[9];
    float* out = (float*)d_out;

    static bool init = false;
    if (!init) {
        cudaFuncSetAttribute(gemm_mma_kernel, cudaFuncAttributeMaxDynamicSharedMemorySize, GSMEM);
        init = true;
    }

    convert_x<<<(M_ROWS * C_DIM / 4) / 256, 256>>>(x);
    convert_w<<<(C_DIM * C_DIM) / 256, 256>>>(Wc);
    gemm_mma_kernel<<<dim3(N_DIM / 128, M_ROWS / 128), 512, GSMEM>>>();
    mask_dot_kernel<<<(P_TOT * 32) / 256, 256>>>(bc, W0, W1, W2);
    finalize_kernel<<<(B_PAT * 3 + 255) / 256, 256>>>(b0, b1, b2, out);
}